// round 13
// baseline (speedup 1.0000x reference)
#include <cuda_runtime.h>
#include <cuda_fp16.h>
#include <mma.h>
#include <cstdint>

using namespace nvcuda;

#define NN 100000
#define NP 100032            // padded to multiple of 64
#define DD 128
#define EE 1600000
#define RR 4

#define SCAN_N   (RR * NN)
#define SCAN_BLK 512
#define SCAN_NBLK ((SCAN_N + SCAN_BLK - 1) / SCAN_BLK)

// ---------------- device scratch --------------------------------------------
__device__ __half  g_Yh[2][(size_t)NP * DD];   // ping-pong fp16 Y (2x25.6MB)
__device__ float   g_h1[(size_t)NN * DD];      // layer-1 output
__device__ float   g_acc[(size_t)NN * DD];     // aggregation accumulator
__device__ int     g_degout[SCAN_N];
__device__ int     g_degin[SCAN_N];
__device__ float   g_rdout[SCAN_N];
__device__ float   g_rdin[SCAN_N];
__device__ int     g_off[SCAN_N];
__device__ int     g_cur[SCAN_N];
__device__ int     g_bsum[SCAN_NBLK];
__device__ float2  g_csr[(size_t)RR * EE];     // (src bits, weight)

// ---------------- setup kernels ---------------------------------------------

__global__ void zero_deg_kernel() {
    int i = blockIdx.x * blockDim.x + threadIdx.x;
    if (i < SCAN_N) { g_degout[i] = 0; g_degin[i] = 0; }
}

__global__ void deg_kernel(const int* __restrict__ src, const int* __restrict__ dst) {
    long long i = (long long)blockIdx.x * blockDim.x + threadIdx.x;
    if (i >= (long long)RR * EE) return;
    int r = (int)(i / EE);
    atomicAdd(&g_degout[r * NN + src[i]], 1);
    atomicAdd(&g_degin[r * NN + dst[i]], 1);
}

__global__ void rsqrt_kernel() {
    int i = blockIdx.x * blockDim.x + threadIdx.x;
    if (i >= SCAN_N) return;
    g_rdout[i] = rsqrtf(fmaxf((float)g_degout[i], 1.f));
    g_rdin[i]  = rsqrtf(fmaxf((float)g_degin[i], 1.f));
}

__global__ void scan_a_kernel() {
    __shared__ int s[SCAN_BLK];
    int i = blockIdx.x * SCAN_BLK + threadIdx.x;
    s[threadIdx.x] = (i < SCAN_N) ? g_degin[i] : 0;
    __syncthreads();
    for (int d = SCAN_BLK / 2; d > 0; d >>= 1) {
        if (threadIdx.x < d) s[threadIdx.x] += s[threadIdx.x + d];
        __syncthreads();
    }
    if (threadIdx.x == 0) g_bsum[blockIdx.x] = s[0];
}

__global__ void scan_b_kernel() {
    __shared__ int s[1024];
    int t = threadIdx.x;
    s[t] = (t < SCAN_NBLK) ? g_bsum[t] : 0;
    __syncthreads();
    for (int d = 1; d < 1024; d <<= 1) {
        int v = (t >= d) ? s[t - d] : 0;
        __syncthreads();
        s[t] += v;
        __syncthreads();
    }
    if (t < SCAN_NBLK) g_bsum[t] = (t == 0) ? 0 : s[t - 1];
}

__global__ void scan_c_kernel() {
    __shared__ int s[SCAN_BLK];
    int i = blockIdx.x * SCAN_BLK + threadIdx.x;
    int v = (i < SCAN_N) ? g_degin[i] : 0;
    s[threadIdx.x] = v;
    __syncthreads();
    for (int d = 1; d < SCAN_BLK; d <<= 1) {
        int u = (threadIdx.x >= d) ? s[threadIdx.x - d] : 0;
        __syncthreads();
        s[threadIdx.x] += u;
        __syncthreads();
    }
    if (i < SCAN_N) {
        int ex = s[threadIdx.x] - v + g_bsum[blockIdx.x];
        g_off[i] = ex;
        g_cur[i] = ex;
    }
}

__global__ void fill_kernel(const int* __restrict__ src, const int* __restrict__ dst,
                            const float* __restrict__ ew) {
    long long i = (long long)blockIdx.x * blockDim.x + threadIdx.x;
    if (i >= (long long)RR * EE) return;
    int r = (int)(i / EE);
    int s = src[i], d = dst[i];
    float w = ew[i] * g_rdout[r * NN + s] * g_rdin[r * NN + d];
    int p = atomicAdd(&g_cur[r * NN + d], 1);
    g_csr[p] = make_float2(__int_as_float(s), w);
}

// ---------------- fp16-split tensor-core GEMM: Yh[y] = half(h @ W_{rbase+y}) -
// grid = (NP/64, 2): two relations per launch, buf = blockIdx.y.
__global__ __launch_bounds__(256) void gemm_fp16_kernel(
    const float* __restrict__ h, const float* __restrict__ Wbase, int rbase)
{
    __shared__ __half sAh[64][40], sAl[64][40];
    __shared__ __half sBh[32][136], sBl[32][136];
    __shared__ float  sStage[8][16][20];

    const int buf = blockIdx.y;
    const float* W = Wbase + (size_t)(rbase + buf) * DD * DD;
    const int row0 = blockIdx.x * 64;
    const int tid = threadIdx.x;
    const int wid = tid >> 5;
    const int lane = tid & 31;
    const int wr = wid & 3;
    const int wc = wid >> 2;

    wmma::fragment<wmma::accumulator, 16, 16, 16, float> acc[4];
#pragma unroll
    for (int i = 0; i < 4; i++) wmma::fill_fragment(acc[i], 0.f);

    for (int kc = 0; kc < DD; kc += 32) {
#pragma unroll
        for (int t = tid; t < 64 * 32; t += 256) {
            int rr = t >> 5, kk = t & 31;
            int n = row0 + rr;
            float a = (n < NN) ? h[(size_t)n * DD + kc + kk] : 0.f;
            __half hi = __float2half_rn(a);
            sAh[rr][kk] = hi;
            sAl[rr][kk] = __float2half_rn(a - __half2float(hi));
        }
#pragma unroll
        for (int t = tid; t < 32 * 128; t += 256) {
            int rr = t >> 7, j = t & 127;
            float b = W[(size_t)(kc + rr) * DD + j];
            __half hi = __float2half_rn(b);
            sBh[rr][j] = hi;
            sBl[rr][j] = __float2half_rn(b - __half2float(hi));
        }
        __syncthreads();

#pragma unroll
        for (int ks = 0; ks < 2; ks++) {
            wmma::fragment<wmma::matrix_a, 16, 16, 16, __half, wmma::row_major> ah, al;
            wmma::load_matrix_sync(ah, &sAh[wr * 16][ks * 16], 40);
            wmma::load_matrix_sync(al, &sAl[wr * 16][ks * 16], 40);
#pragma unroll
            for (int cg = 0; cg < 4; cg++) {
                int col = wc * 64 + cg * 16;
                wmma::fragment<wmma::matrix_b, 16, 16, 16, __half, wmma::row_major> bh, bl;
                wmma::load_matrix_sync(bh, &sBh[ks * 16][col], 136);
                wmma::load_matrix_sync(bl, &sBl[ks * 16][col], 136);
                wmma::mma_sync(acc[cg], ah, bh, acc[cg]);
                wmma::mma_sync(acc[cg], ah, bl, acc[cg]);
                wmma::mma_sync(acc[cg], al, bh, acc[cg]);
            }
        }
        __syncthreads();
    }

    const int rr = lane >> 1;
    const int cb = (lane & 1) * 8;
    __half* Yout = g_Yh[buf];
#pragma unroll
    for (int cg = 0; cg < 4; cg++) {
        wmma::store_matrix_sync(&sStage[wid][0][0], acc[cg], 20, wmma::mem_row_major);
        __syncwarp();
        const float* sp = &sStage[wid][rr][cb];
        __half2 h0 = __floats2half2_rn(sp[0], sp[1]);
        __half2 h1 = __floats2half2_rn(sp[2], sp[3]);
        __half2 h2 = __floats2half2_rn(sp[4], sp[5]);
        __half2 h3 = __floats2half2_rn(sp[6], sp[7]);
        int grow = row0 + wr * 16 + rr;
        int gcol = wc * 64 + cg * 16 + cb;
        __half2 pack[4] = {h0, h1, h2, h3};
        *(uint4*)(Yout + (size_t)grow * DD + gcol) = *(const uint4*)pack;
        __syncwarp();
    }
}

// ---------------- pair pull: two relations per launch ------------------------
// Warp per node; accumulates relations rbase and rbase+1 in registers.
// first=1: write acc (no read). first=0: read acc once, add, bias+relu -> out.
__global__ __launch_bounds__(256) void pull2_kernel(
    int rbase, int first, const float* __restrict__ b, float* __restrict__ out)
{
    __shared__ float bsum[DD];
    if (!first && threadIdx.x < DD)
        bsum[threadIdx.x] = b[threadIdx.x] + b[DD + threadIdx.x]
                          + b[2 * DD + threadIdx.x] + b[3 * DD + threadIdx.x];
    if (!first) __syncthreads();

    int warp = (blockIdx.x * blockDim.x + threadIdx.x) >> 5;
    int lane = threadIdx.x & 31;
    if (warp >= NN) return;
    const int co = lane * 4;

    float4 a0 = make_float4(0.f, 0.f, 0.f, 0.f);

#pragma unroll
    for (int rr = 0; rr < 2; rr++) {
        int idx = (rbase + rr) * NN + warp;
        const float2* eb = g_csr + g_off[idx];
        int cnt = g_degin[idx];
        const __half* Y = g_Yh[rr];

        for (int j = 0; j < cnt; j += 32) {
            int m = cnt - j; if (m > 32) m = 32;
            float2 er = (lane < m) ? __ldcs(&eb[j + lane]) : make_float2(0.f, 0.f);
            int si = __float_as_int(er.x);
#pragma unroll 8
            for (int k = 0; k < m; k++) {
                int s   = __shfl_sync(0xffffffffu, si, k);
                float w = __shfl_sync(0xffffffffu, er.y, k);
                uint2 rv = *(const uint2*)(Y + (size_t)s * DD + co);
                float2 f0 = __half22float2(*(__half2*)&rv.x);
                float2 f1 = __half22float2(*(__half2*)&rv.y);
                a0.x += f0.x * w; a0.y += f0.y * w; a0.z += f1.x * w; a0.w += f1.y * w;
            }
        }
    }

    if (first) {
        *(float4*)(g_acc + (size_t)warp * DD + co) = a0;
    } else {
        float4 old = *(const float4*)(g_acc + (size_t)warp * DD + co);
        float4 o;
        o.x = fmaxf(a0.x + old.x + bsum[co],     0.f);
        o.y = fmaxf(a0.y + old.y + bsum[co + 1], 0.f);
        o.z = fmaxf(a0.z + old.z + bsum[co + 2], 0.f);
        o.w = fmaxf(a0.w + old.w + bsum[co + 3], 0.f);
        *(float4*)(out + (size_t)warp * DD + co) = o;
    }
}

// ---------------- launch ----------------------------------------------------

extern "C" void kernel_launch(void* const* d_in, const int* in_sizes, int n_in,
                              void* d_out, int out_size)
{
    const float* x   = (const float*)d_in[0];
    const int*   src = (const int*)d_in[1];
    const int*   dst = (const int*)d_in[2];
    const float* ew  = (const float*)d_in[3];
    const float* W1  = (const float*)d_in[4];
    const float* b1  = (const float*)d_in[5];
    const float* W2  = (const float*)d_in[6];
    const float* b2  = (const float*)d_in[7];
    float* out = (float*)d_out;

    const int T = 256;
    const long long RE = (long long)RR * EE;
    const int edge_blocks = (int)((RE + T - 1) / T);

    // ---- setup (graph identical for both layers) ----
    zero_deg_kernel<<<(SCAN_N + T - 1) / T, T>>>();
    deg_kernel<<<edge_blocks, T>>>(src, dst);
    rsqrt_kernel<<<(SCAN_N + T - 1) / T, T>>>();
    scan_a_kernel<<<SCAN_NBLK, SCAN_BLK>>>();
    scan_b_kernel<<<1, 1024>>>();
    scan_c_kernel<<<SCAN_NBLK, SCAN_BLK>>>();
    fill_kernel<<<edge_blocks, T>>>(src, dst, ew);

    dim3 ggrid(NP / 64, 2);
    const int pull_blocks = (NN * 32 + T - 1) / T;

    for (int l = 0; l < 2; l++) {
        const float* h = (l == 0) ? x  : g_h1;
        const float* W = (l == 0) ? W1 : W2;
        const float* b = (l == 0) ? b1 : b2;
        float* o       = (l == 0) ? g_h1 : out;

        gemm_fp16_kernel<<<ggrid, T>>>(h, W, 0);
        pull2_kernel<<<pull_blocks, T>>>(0, 1, b, o);
        gemm_fp16_kernel<<<ggrid, T>>>(h, W, 2);
        pull2_kernel<<<pull_blocks, T>>>(2, 0, b, o);
    }
}

// round 14
// speedup vs baseline: 1.0765x; 1.0765x over previous
#include <cuda_runtime.h>
#include <cuda_fp16.h>
#include <mma.h>
#include <cstdint>

using namespace nvcuda;

#define NN 100000
#define NP 100032            // padded to multiple of 64
#define DD 128
#define EE 1600000
#define RR 4

#define SCAN_N   (RR * NN)
#define SCAN_BLK 512
#define SCAN_NBLK ((SCAN_N + SCAN_BLK - 1) / SCAN_BLK)

// ---------------- device scratch --------------------------------------------
__device__ __half  g_Yh[(size_t)NP * DD];      // transformed feats (fp16, 25.6MB)
__device__ float   g_h1[(size_t)NN * DD];      // layer-1 output
__device__ float   g_acc[(size_t)NN * DD];     // aggregation accumulator
__device__ int     g_degout[SCAN_N];
__device__ int     g_degin[SCAN_N];
__device__ int     g_off[SCAN_N];
__device__ int     g_cur[SCAN_N];
__device__ int     g_bsum[SCAN_NBLK];
__device__ float2  g_csr[(size_t)RR * EE];     // (src bits, weight)

// ---------------- setup kernels ---------------------------------------------

__global__ void deg_kernel(const int* __restrict__ src, const int* __restrict__ dst) {
    long long i = (long long)blockIdx.x * blockDim.x + threadIdx.x;
    if (i >= (long long)RR * EE) return;
    int r = (int)(i / EE);
    atomicAdd(&g_degout[r * NN + src[i]], 1);
    atomicAdd(&g_degin[r * NN + dst[i]], 1);
}

__global__ void scan_a_kernel() {
    __shared__ int s[SCAN_BLK];
    int i = blockIdx.x * SCAN_BLK + threadIdx.x;
    s[threadIdx.x] = (i < SCAN_N) ? g_degin[i] : 0;
    __syncthreads();
    for (int d = SCAN_BLK / 2; d > 0; d >>= 1) {
        if (threadIdx.x < d) s[threadIdx.x] += s[threadIdx.x + d];
        __syncthreads();
    }
    if (threadIdx.x == 0) g_bsum[blockIdx.x] = s[0];
}

__global__ void scan_b_kernel() {
    __shared__ int s[1024];
    int t = threadIdx.x;
    s[t] = (t < SCAN_NBLK) ? g_bsum[t] : 0;
    __syncthreads();
    for (int d = 1; d < 1024; d <<= 1) {
        int v = (t >= d) ? s[t - d] : 0;
        __syncthreads();
        s[t] += v;
        __syncthreads();
    }
    if (t < SCAN_NBLK) g_bsum[t] = (t == 0) ? 0 : s[t - 1];
}

__global__ void scan_c_kernel() {
    __shared__ int s[SCAN_BLK];
    int i = blockIdx.x * SCAN_BLK + threadIdx.x;
    int v = (i < SCAN_N) ? g_degin[i] : 0;
    s[threadIdx.x] = v;
    __syncthreads();
    for (int d = 1; d < SCAN_BLK; d <<= 1) {
        int u = (threadIdx.x >= d) ? s[threadIdx.x - d] : 0;
        __syncthreads();
        s[threadIdx.x] += u;
        __syncthreads();
    }
    if (i < SCAN_N) {
        int ex = s[threadIdx.x] - v + g_bsum[blockIdx.x];
        g_off[i] = ex;
        g_cur[i] = ex;
    }
}

// fill with fused degree-normalization (rsqrt folded in; no rd arrays)
__global__ void fill_kernel(const int* __restrict__ src, const int* __restrict__ dst,
                            const float* __restrict__ ew) {
    long long i = (long long)blockIdx.x * blockDim.x + threadIdx.x;
    if (i >= (long long)RR * EE) return;
    int r = (int)(i / EE);
    int s = src[i], d = dst[i];
    float w = ew[i]
            * rsqrtf(fmaxf((float)g_degout[r * NN + s], 1.f))
            * rsqrtf(fmaxf((float)g_degin[r * NN + d], 1.f));
    int p = atomicAdd(&g_cur[r * NN + d], 1);
    g_csr[p] = make_float2(__int_as_float(s), w);
}

// ---------------- fp16-split tensor-core GEMM: Yh = half(h @ W) --------------
__global__ __launch_bounds__(256) void gemm_fp16_kernel(
    const float* __restrict__ h, const float* __restrict__ W)
{
    __shared__ __half sAh[64][40], sAl[64][40];
    __shared__ __half sBh[32][136], sBl[32][136];
    __shared__ float  sStage[8][16][20];

    const int row0 = blockIdx.x * 64;
    const int tid = threadIdx.x;
    const int wid = tid >> 5;
    const int lane = tid & 31;
    const int wr = wid & 3;
    const int wc = wid >> 2;

    wmma::fragment<wmma::accumulator, 16, 16, 16, float> acc[4];
#pragma unroll
    for (int i = 0; i < 4; i++) wmma::fill_fragment(acc[i], 0.f);

    for (int kc = 0; kc < DD; kc += 32) {
#pragma unroll
        for (int t = tid; t < 64 * 32; t += 256) {
            int rr = t >> 5, kk = t & 31;
            int n = row0 + rr;
            float a = (n < NN) ? h[(size_t)n * DD + kc + kk] : 0.f;
            __half hi = __float2half_rn(a);
            sAh[rr][kk] = hi;
            sAl[rr][kk] = __float2half_rn(a - __half2float(hi));
        }
#pragma unroll
        for (int t = tid; t < 32 * 128; t += 256) {
            int rr = t >> 7, j = t & 127;
            float b = W[(size_t)(kc + rr) * DD + j];
            __half hi = __float2half_rn(b);
            sBh[rr][j] = hi;
            sBl[rr][j] = __float2half_rn(b - __half2float(hi));
        }
        __syncthreads();

#pragma unroll
        for (int ks = 0; ks < 2; ks++) {
            wmma::fragment<wmma::matrix_a, 16, 16, 16, __half, wmma::row_major> ah, al;
            wmma::load_matrix_sync(ah, &sAh[wr * 16][ks * 16], 40);
            wmma::load_matrix_sync(al, &sAl[wr * 16][ks * 16], 40);
#pragma unroll
            for (int cg = 0; cg < 4; cg++) {
                int col = wc * 64 + cg * 16;
                wmma::fragment<wmma::matrix_b, 16, 16, 16, __half, wmma::row_major> bh, bl;
                wmma::load_matrix_sync(bh, &sBh[ks * 16][col], 136);
                wmma::load_matrix_sync(bl, &sBl[ks * 16][col], 136);
                wmma::mma_sync(acc[cg], ah, bh, acc[cg]);
                wmma::mma_sync(acc[cg], ah, bl, acc[cg]);
                wmma::mma_sync(acc[cg], al, bh, acc[cg]);
            }
        }
        __syncthreads();
    }

    const int rr = lane >> 1;
    const int cb = (lane & 1) * 8;
#pragma unroll
    for (int cg = 0; cg < 4; cg++) {
        wmma::store_matrix_sync(&sStage[wid][0][0], acc[cg], 20, wmma::mem_row_major);
        __syncwarp();
        const float* sp = &sStage[wid][rr][cb];
        __half2 h0 = __floats2half2_rn(sp[0], sp[1]);
        __half2 h1 = __floats2half2_rn(sp[2], sp[3]);
        __half2 h2 = __floats2half2_rn(sp[4], sp[5]);
        __half2 h3 = __floats2half2_rn(sp[6], sp[7]);
        int grow = row0 + wr * 16 + rr;
        int gcol = wc * 64 + cg * 16 + cb;
        __half2 pack[4] = {h0, h1, h2, h3};
        *(uint4*)(g_Yh + (size_t)grow * DD + gcol) = *(const uint4*)pack;
        __syncwarp();
    }
}

// ---------------- per-relation pull: two nodes per warp ----------------------
// Warp handles nodes 2w and 2w+1 with interleaved, branchless gather streams
// (zero-filled lanes make dead edges gather row 0 with weight 0) -> 2x MLP.
__global__ __launch_bounds__(256) void pull_r_kernel(int r, int first)
{
    int w_id = (blockIdx.x * blockDim.x + threadIdx.x) >> 5;
    int lane = threadIdx.x & 31;
    int n0 = w_id * 2;
    if (n0 >= NN) return;
    int n1 = n0 + 1;                       // NN even -> always valid
    const int co = lane * 4;

    int idx0 = r * NN + n0;
    int idx1 = r * NN + n1;
    const float2* eb0 = g_csr + g_off[idx0];
    const float2* eb1 = g_csr + g_off[idx1];
    int cnt0 = g_degin[idx0];
    int cnt1 = g_degin[idx1];
    int mm = max(cnt0, cnt1);

    float4 a0 = make_float4(0.f, 0.f, 0.f, 0.f);
    float4 a1 = make_float4(0.f, 0.f, 0.f, 0.f);

    for (int j = 0; j < mm; j += 32) {
        int m0 = cnt0 - j; m0 = m0 < 0 ? 0 : (m0 > 32 ? 32 : m0);
        int m1 = cnt1 - j; m1 = m1 < 0 ? 0 : (m1 > 32 ? 32 : m1);
        int mb = m0 > m1 ? m0 : m1;
        float2 er0 = (lane < m0) ? eb0[j + lane] : make_float2(0.f, 0.f);
        float2 er1 = (lane < m1) ? eb1[j + lane] : make_float2(0.f, 0.f);
        int si0 = __float_as_int(er0.x);
        int si1 = __float_as_int(er1.x);
#pragma unroll 4
        for (int k = 0; k < mb; k++) {
            int s0   = __shfl_sync(0xffffffffu, si0, k);
            float w0 = __shfl_sync(0xffffffffu, er0.y, k);
            int s1   = __shfl_sync(0xffffffffu, si1, k);
            float w1 = __shfl_sync(0xffffffffu, er1.y, k);
            uint2 rv0 = *(const uint2*)(g_Yh + (size_t)s0 * DD + co);
            uint2 rv1 = *(const uint2*)(g_Yh + (size_t)s1 * DD + co);
            float2 f00 = __half22float2(*(__half2*)&rv0.x);
            float2 f01 = __half22float2(*(__half2*)&rv0.y);
            float2 f10 = __half22float2(*(__half2*)&rv1.x);
            float2 f11 = __half22float2(*(__half2*)&rv1.y);
            a0.x += f00.x * w0; a0.y += f00.y * w0; a0.z += f01.x * w0; a0.w += f01.y * w0;
            a1.x += f10.x * w1; a1.y += f10.y * w1; a1.z += f11.x * w1; a1.w += f11.y * w1;
        }
    }

    float* p0 = g_acc + (size_t)n0 * DD + co;
    float* p1 = g_acc + (size_t)n1 * DD + co;
    if (!first) {
        float4 o0 = *(const float4*)p0;
        float4 o1 = *(const float4*)p1;
        a0.x += o0.x; a0.y += o0.y; a0.z += o0.z; a0.w += o0.w;
        a1.x += o1.x; a1.y += o1.y; a1.z += o1.z; a1.w += o1.w;
    }
    *(float4*)p0 = a0;
    *(float4*)p1 = a1;
}

// out[n][j] = relu(acc[n][j] + sum_r b[r][j])
__global__ void bias_relu_kernel(const float* __restrict__ b, float* __restrict__ out) {
    int i = blockIdx.x * blockDim.x + threadIdx.x;
    if (i >= NN * DD) return;
    int j = i & (DD - 1);
    float bs = b[j] + b[DD + j] + b[2 * DD + j] + b[3 * DD + j];
    out[i] = fmaxf(g_acc[i] + bs, 0.f);
}

// ---------------- launch ----------------------------------------------------

static void* s_degout_ptr = nullptr;
static void* s_degin_ptr  = nullptr;

extern "C" void kernel_launch(void* const* d_in, const int* in_sizes, int n_in,
                              void* d_out, int out_size)
{
    if (!s_degout_ptr) {
        cudaGetSymbolAddress(&s_degout_ptr, g_degout);
        cudaGetSymbolAddress(&s_degin_ptr,  g_degin);
    }

    const float* x   = (const float*)d_in[0];
    const int*   src = (const int*)d_in[1];
    const int*   dst = (const int*)d_in[2];
    const float* ew  = (const float*)d_in[3];
    const float* W1  = (const float*)d_in[4];
    const float* b1  = (const float*)d_in[5];
    const float* W2  = (const float*)d_in[6];
    const float* b2  = (const float*)d_in[7];
    float* out = (float*)d_out;

    const int T = 256;
    const long long RE = (long long)RR * EE;
    const int edge_blocks = (int)((RE + T - 1) / T);
    const int ggrid = NP / 64;
    const int pull_blocks = ((NN / 2) * 32 + T - 1) / T;
    const int elem_blocks = (NN * DD + T - 1) / T;

    // zero degree arrays via memset nodes (not kernel launches)
    cudaMemsetAsync(s_degout_ptr, 0, SCAN_N * sizeof(int));
    cudaMemsetAsync(s_degin_ptr,  0, SCAN_N * sizeof(int));

    deg_kernel<<<edge_blocks, T>>>(src, dst);                 // launch 0
    scan_a_kernel<<<SCAN_NBLK, SCAN_BLK>>>();                 // launch 1
    scan_b_kernel<<<1, 1024>>>();                             // launch 2
    gemm_fp16_kernel<<<ggrid, T>>>(x, W1);                    // launch 3 (profiled)
    scan_c_kernel<<<SCAN_NBLK, SCAN_BLK>>>();                 // launch 4
    fill_kernel<<<edge_blocks, T>>>(src, dst, ew);            // launch 5

    // ---- layer 1 (gemm for r=0 already issued above) ----
    pull_r_kernel<<<pull_blocks, T>>>(0, 1);
    for (int r = 1; r < RR; r++) {
        gemm_fp16_kernel<<<ggrid, T>>>(x, W1 + (size_t)r * DD * DD);
        pull_r_kernel<<<pull_blocks, T>>>(r, 0);
    }
    bias_relu_kernel<<<elem_blocks, T>>>(b1, g_h1);

    // ---- layer 2 ----
    for (int r = 0; r < RR; r++) {
        gemm_fp16_kernel<<<ggrid, T>>>(g_h1, W2 + (size_t)r * DD * DD);
        pull_r_kernel<<<pull_blocks, T>>>(r, r == 0);
    }
    bias_relu_kernel<<<elem_blocks, T>>>(b2, out);
}

// round 15
// speedup vs baseline: 1.4219x; 1.3209x over previous
#include <cuda_runtime.h>
#include <cuda_fp16.h>
#include <mma.h>
#include <cstdint>

using namespace nvcuda;

#define NN 100000
#define NP 100032            // padded to multiple of 64
#define DD 128
#define EE 1600000
#define RR 4

#define SCAN_N   (RR * NN)
#define SCAN_BLK 512
#define SCAN_NBLK ((SCAN_N + SCAN_BLK - 1) / SCAN_BLK)

// ---------------- device scratch --------------------------------------------
__device__ __half  g_Yh[(size_t)NP * DD];      // transformed feats (fp16, 25.6MB)
__device__ __half  g_Ah[(size_t)NP * DD];      // input feats hi (fp16)
__device__ __half  g_Al[(size_t)NP * DD];      // input feats lo (fp16)
__device__ __half  g_Bh[2][(size_t)RR * DD * DD];  // W hi per layer
__device__ __half  g_Bl[2][(size_t)RR * DD * DD];  // W lo per layer
__device__ float   g_acc[(size_t)NN * DD];     // aggregation accumulator
__device__ int     g_deg[2 * SCAN_N];          // [0]=degout, [SCAN_N]=degin
__device__ int     g_off[SCAN_N];
__device__ int     g_cur[SCAN_N];
__device__ int     g_bsum[SCAN_NBLK];
__device__ float2  g_csr[(size_t)RR * EE];     // (src bits, weight)

// ---------------- operand pre-split ------------------------------------------
// dst{h,l}[i] = fp16 split of src[i]; zero beyond nvalid (all sizes mult of 4)
__global__ void presplit_kernel(const float* __restrict__ src,
                                __half* __restrict__ dh, __half* __restrict__ dl,
                                int nvalid4, int ntotal4) {
    int i = blockIdx.x * blockDim.x + threadIdx.x;
    if (i >= ntotal4) return;
    float4 v = (i < nvalid4) ? ((const float4*)src)[i]
                             : make_float4(0.f, 0.f, 0.f, 0.f);
    __half h0 = __float2half_rn(v.x), h1 = __float2half_rn(v.y);
    __half h2 = __float2half_rn(v.z), h3 = __float2half_rn(v.w);
    __half l0 = __float2half_rn(v.x - __half2float(h0));
    __half l1 = __float2half_rn(v.y - __half2float(h1));
    __half l2 = __float2half_rn(v.z - __half2float(h2));
    __half l3 = __float2half_rn(v.w - __half2float(h3));
    __half2 ph[2] = {__halves2half2(h0, h1), __halves2half2(h2, h3)};
    __half2 pl[2] = {__halves2half2(l0, l1), __halves2half2(l2, l3)};
    ((uint2*)dh)[i] = *(const uint2*)ph;
    ((uint2*)dl)[i] = *(const uint2*)pl;
}

// ---------------- setup kernels ---------------------------------------------

__global__ void deg_kernel(const int* __restrict__ src, const int* __restrict__ dst) {
    long long i = (long long)blockIdx.x * blockDim.x + threadIdx.x;
    if (i >= (long long)RR * EE) return;
    int r = (int)(i / EE);
    atomicAdd(&g_deg[r * NN + src[i]], 1);
    atomicAdd(&g_deg[SCAN_N + r * NN + dst[i]], 1);
}

__global__ void scan_a_kernel() {
    __shared__ int s[SCAN_BLK];
    int i = blockIdx.x * SCAN_BLK + threadIdx.x;
    s[threadIdx.x] = (i < SCAN_N) ? g_deg[SCAN_N + i] : 0;
    __syncthreads();
    for (int d = SCAN_BLK / 2; d > 0; d >>= 1) {
        if (threadIdx.x < d) s[threadIdx.x] += s[threadIdx.x + d];
        __syncthreads();
    }
    if (threadIdx.x == 0) g_bsum[blockIdx.x] = s[0];
}

__global__ void scan_b_kernel() {
    __shared__ int s[1024];
    int t = threadIdx.x;
    s[t] = (t < SCAN_NBLK) ? g_bsum[t] : 0;
    __syncthreads();
    for (int d = 1; d < 1024; d <<= 1) {
        int v = (t >= d) ? s[t - d] : 0;
        __syncthreads();
        s[t] += v;
        __syncthreads();
    }
    if (t < SCAN_NBLK) g_bsum[t] = (t == 0) ? 0 : s[t - 1];
}

__global__ void scan_c_kernel() {
    __shared__ int s[SCAN_BLK];
    int i = blockIdx.x * SCAN_BLK + threadIdx.x;
    int v = (i < SCAN_N) ? g_deg[SCAN_N + i] : 0;
    s[threadIdx.x] = v;
    __syncthreads();
    for (int d = 1; d < SCAN_BLK; d <<= 1) {
        int u = (threadIdx.x >= d) ? s[threadIdx.x - d] : 0;
        __syncthreads();
        s[threadIdx.x] += u;
        __syncthreads();
    }
    if (i < SCAN_N) {
        int ex = s[threadIdx.x] - v + g_bsum[blockIdx.x];
        g_off[i] = ex;
        g_cur[i] = ex;
    }
}

__global__ void fill_kernel(const int* __restrict__ src, const int* __restrict__ dst,
                            const float* __restrict__ ew) {
    long long i = (long long)blockIdx.x * blockDim.x + threadIdx.x;
    if (i >= (long long)RR * EE) return;
    int r = (int)(i / EE);
    int s = src[i], d = dst[i];
    float w = ew[i]
            * rsqrtf(fmaxf((float)g_deg[r * NN + s], 1.f))
            * rsqrtf(fmaxf((float)g_deg[SCAN_N + r * NN + d], 1.f));
    int p = atomicAdd(&g_cur[r * NN + d], 1);
    g_csr[p] = make_float2(__int_as_float(s), w);
}

// ---------------- sync-free fp16-split GEMM: Yh = half(A @ W) ----------------
// Operands pre-split fp16; fragments loaded straight from global (W pair is
// 64KB -> L1-resident; A tile reuse L1-served). NO __syncthreads in mainloop.
__global__ __launch_bounds__(256) void gemm_fp16_kernel(
    const __half* __restrict__ Ah, const __half* __restrict__ Al,
    const __half* __restrict__ Bh, const __half* __restrict__ Bl)
{
    __shared__ float sStage[8][16][20];

    const int row0 = blockIdx.x * 64;
    const int tid = threadIdx.x;
    const int wid = tid >> 5;
    const int lane = tid & 31;
    const int wr = wid & 3;
    const int wc = wid >> 2;

    const __half* Ap = Ah + (size_t)(row0 + wr * 16) * DD;
    const __half* Alp = Al + (size_t)(row0 + wr * 16) * DD;

    wmma::fragment<wmma::accumulator, 16, 16, 16, float> acc[4];
#pragma unroll
    for (int i = 0; i < 4; i++) wmma::fill_fragment(acc[i], 0.f);

#pragma unroll
    for (int kc = 0; kc < DD; kc += 16) {
        wmma::fragment<wmma::matrix_a, 16, 16, 16, __half, wmma::row_major> ah, al;
        wmma::load_matrix_sync(ah, Ap + kc, DD);
        wmma::load_matrix_sync(al, Alp + kc, DD);
#pragma unroll
        for (int cg = 0; cg < 4; cg++) {
            int col = wc * 64 + cg * 16;
            wmma::fragment<wmma::matrix_b, 16, 16, 16, __half, wmma::row_major> bh, bl;
            wmma::load_matrix_sync(bh, Bh + (size_t)kc * DD + col, DD);
            wmma::load_matrix_sync(bl, Bl + (size_t)kc * DD + col, DD);
            wmma::mma_sync(acc[cg], ah, bh, acc[cg]);
            wmma::mma_sync(acc[cg], ah, bl, acc[cg]);
            wmma::mma_sync(acc[cg], al, bh, acc[cg]);
        }
    }

    const int rr = lane >> 1;
    const int cb = (lane & 1) * 8;
#pragma unroll
    for (int cg = 0; cg < 4; cg++) {
        wmma::store_matrix_sync(&sStage[wid][0][0], acc[cg], 20, wmma::mem_row_major);
        __syncwarp();
        const float* sp = &sStage[wid][rr][cb];
        __half2 h0 = __floats2half2_rn(sp[0], sp[1]);
        __half2 h1 = __floats2half2_rn(sp[2], sp[3]);
        __half2 h2 = __floats2half2_rn(sp[4], sp[5]);
        __half2 h3 = __floats2half2_rn(sp[6], sp[7]);
        int grow = row0 + wr * 16 + rr;
        int gcol = wc * 64 + cg * 16 + cb;
        __half2 pack[4] = {h0, h1, h2, h3};
        *(uint4*)(g_Yh + (size_t)grow * DD + gcol) = *(const uint4*)pack;
        __syncwarp();
    }
}

// ---------------- per-relation pull (R11 proven shape) -----------------------
__global__ __launch_bounds__(256) void pull_r_kernel(int r, int first)
{
    int warp = (blockIdx.x * blockDim.x + threadIdx.x) >> 5;
    int lane = threadIdx.x & 31;
    if (warp >= NN) return;
    int idx = r * NN + warp;
    const float2* eb = g_csr + g_off[idx];
    int cnt = g_deg[SCAN_N + idx];
    const int co = lane * 4;

    float4 a0 = make_float4(0.f, 0.f, 0.f, 0.f);

    for (int j = 0; j < cnt; j += 32) {
        int m = cnt - j; if (m > 32) m = 32;
        float2 er = (lane < m) ? eb[j + lane] : make_float2(0.f, 0.f);
        int si = __float_as_int(er.x);
#pragma unroll 8
        for (int k = 0; k < m; k++) {
            int s  = __shfl_sync(0xffffffffu, si, k);
            float w = __shfl_sync(0xffffffffu, er.y, k);
            uint2 rv = *(const uint2*)(g_Yh + (size_t)s * DD + co);
            float2 f0 = __half22float2(*(__half2*)&rv.x);
            float2 f1 = __half22float2(*(__half2*)&rv.y);
            a0.x += f0.x * w; a0.y += f0.y * w; a0.z += f1.x * w; a0.w += f1.y * w;
        }
    }

    float* accp = g_acc + (size_t)warp * DD + co;
    if (!first) {
        float4 old = *(const float4*)accp;
        a0.x += old.x; a0.y += old.y; a0.z += old.z; a0.w += old.w;
    }
    *(float4*)accp = a0;
}

// layer-1 epilogue: h1 = relu(acc + bsum), written directly as fp16 hi/lo split
__global__ void bias_relu_split_kernel(const float* __restrict__ b) {
    int i = blockIdx.x * blockDim.x + threadIdx.x;
    if (i >= NN * DD / 4) return;
    int c = (i * 4) & (DD - 1);
    float4 v = ((const float4*)g_acc)[i];
    float o0 = fmaxf(v.x + b[c]   + b[DD + c]   + b[2*DD + c]   + b[3*DD + c],   0.f);
    float o1 = fmaxf(v.y + b[c+1] + b[DD + c+1] + b[2*DD + c+1] + b[3*DD + c+1], 0.f);
    float o2 = fmaxf(v.z + b[c+2] + b[DD + c+2] + b[2*DD + c+2] + b[3*DD + c+2], 0.f);
    float o3 = fmaxf(v.w + b[c+3] + b[DD + c+3] + b[2*DD + c+3] + b[3*DD + c+3], 0.f);
    __half h0 = __float2half_rn(o0), h1 = __float2half_rn(o1);
    __half h2 = __float2half_rn(o2), h3 = __float2half_rn(o3);
    __half l0 = __float2half_rn(o0 - __half2float(h0));
    __half l1 = __float2half_rn(o1 - __half2float(h1));
    __half l2 = __float2half_rn(o2 - __half2float(h2));
    __half l3 = __float2half_rn(o3 - __half2float(h3));
    __half2 ph[2] = {__halves2half2(h0, h1), __halves2half2(h2, h3)};
    __half2 pl[2] = {__halves2half2(l0, l1), __halves2half2(l2, l3)};
    ((uint2*)g_Ah)[i] = *(const uint2*)ph;
    ((uint2*)g_Al)[i] = *(const uint2*)pl;
}

// layer-2 epilogue: out = relu(acc + bsum) fp32
__global__ void bias_relu_kernel(const float* __restrict__ b, float* __restrict__ out) {
    int i = blockIdx.x * blockDim.x + threadIdx.x;
    if (i >= NN * DD) return;
    int j = i & (DD - 1);
    float bs = b[j] + b[DD + j] + b[2 * DD + j] + b[3 * DD + j];
    out[i] = fmaxf(g_acc[i] + bs, 0.f);
}

// ---------------- launch ----------------------------------------------------

static void* s_deg_ptr = nullptr;

extern "C" void kernel_launch(void* const* d_in, const int* in_sizes, int n_in,
                              void* d_out, int out_size)
{
    if (!s_deg_ptr) cudaGetSymbolAddress(&s_deg_ptr, g_deg);

    const float* x   = (const float*)d_in[0];
    const int*   src = (const int*)d_in[1];
    const int*   dst = (const int*)d_in[2];
    const float* ew  = (const float*)d_in[3];
    const float* W1  = (const float*)d_in[4];
    const float* b1  = (const float*)d_in[5];
    const float* W2  = (const float*)d_in[6];
    const float* b2  = (const float*)d_in[7];
    float* out = (float*)d_out;

    const int T = 256;
    const long long RE = (long long)RR * EE;
    const int edge_blocks = (int)((RE + T - 1) / T);
    const int ggrid = NP / 64;
    const int pull_blocks = (NN * 32 + T - 1) / T;
    const int elem_blocks = (NN * DD + T - 1) / T;
    const int hsplit_blocks = (NP * DD / 4 + T - 1) / T;
    const int wsplit_blocks = (RR * DD * DD / 4 + T - 1) / T;

    __half *Ah, *Al, *Bh0, *Bl0, *Bh1, *Bl1;
    cudaGetSymbolAddress((void**)&Ah, g_Ah);
    cudaGetSymbolAddress((void**)&Al, g_Al);
    cudaGetSymbolAddress((void**)&Bh0, g_Bh);  Bh1 = Bh0 + (size_t)RR * DD * DD;
    cudaGetSymbolAddress((void**)&Bl0, g_Bl);  Bl1 = Bl0 + (size_t)RR * DD * DD;

    // launches 0..5 (slot 5 = first GEMM, profiled)
    cudaMemsetAsync(s_deg_ptr, 0, 2 * SCAN_N * sizeof(int));              // 0
    presplit_kernel<<<hsplit_blocks, T>>>(x, Ah, Al, NN*DD/4, NP*DD/4);   // 1
    presplit_kernel<<<wsplit_blocks, T>>>(W1, Bh0, Bl0, RR*DD*DD/4, RR*DD*DD/4); // 2
    presplit_kernel<<<wsplit_blocks, T>>>(W2, Bh1, Bl1, RR*DD*DD/4, RR*DD*DD/4); // 3
    deg_kernel<<<edge_blocks, T>>>(src, dst);                             // 4
    gemm_fp16_kernel<<<ggrid, T>>>(Ah, Al, Bh0, Bl0);                     // 5 (r=0)
    scan_a_kernel<<<SCAN_NBLK, SCAN_BLK>>>();
    scan_b_kernel<<<1, 1024>>>();
    scan_c_kernel<<<SCAN_NBLK, SCAN_BLK>>>();
    fill_kernel<<<edge_blocks, T>>>(src, dst, ew);

    // ---- layer 1 (gemm r=0 already issued) ----
    pull_r_kernel<<<pull_blocks, T>>>(0, 1);
    for (int r = 1; r < RR; r++) {
        gemm_fp16_kernel<<<ggrid, T>>>(Ah, Al,
                                       Bh0 + (size_t)r * DD * DD,
                                       Bl0 + (size_t)r * DD * DD);
        pull_r_kernel<<<pull_blocks, T>>>(r, 0);
    }
    bias_relu_split_kernel<<<(NN * DD / 4 + T - 1) / T, T>>>(b1);

    // ---- layer 2 ----
    for (int r = 0; r < RR; r++) {
        gemm_fp16_kernel<<<ggrid, T>>>(Ah, Al,
                                       Bh1 + (size_t)r * DD * DD,
                                       Bl1 + (size_t)r * DD * DD);
        pull_r_kernel<<<pull_blocks, T>>>(r, r == 0);
    }
    bias_relu_kernel<<<elem_blocks, T>>>(b2, out);
}